// round 1
// baseline (speedup 1.0000x reference)
#include <cuda_runtime.h>

#define B   2
#define NQ  900
#define HW  256      // 16*16 argmax domain
#define E   256      // embed dim
#define NH  8        // heads
#define MAXD2 451    // dx^2+dy^2, dx,dy in [-15,15] -> max 225+225=450

// Scratch (no allocations allowed -> __device__ globals)
__device__ unsigned char g_cell[B * NQ];   // argmax cell index (iy*16+ix) per (b,q)
__device__ int           g_cnt[B * HW];    // cell histogram per batch
__device__ float         g_lut[B * MAXD2]; // bias_mean as function of integer d2

// ---------------------------------------------------------------------------
// Kernel 0: zero histogram
// ---------------------------------------------------------------------------
__global__ void k_init() {
    int t = blockIdx.x * blockDim.x + threadIdx.x;
    if (t < B * HW) g_cnt[t] = 0;
}

// ---------------------------------------------------------------------------
// Kernel 1: per-(b,q) argmax over 256 values (one warp each), first-index
// tiebreak to match jnp.argmax. Also builds the cell histogram.
// ---------------------------------------------------------------------------
__global__ void k_argmax(const float* __restrict__ rp) {
    int gw   = (blockIdx.x * blockDim.x + threadIdx.x) >> 5;  // global warp id
    int lane = threadIdx.x & 31;
    if (gw >= B * NQ) return;

    const float* p = rp + (size_t)gw * HW;
    float best = -__int_as_float(0x7f800000); // -inf
    int   bi   = 0;
    #pragma unroll
    for (int k = 0; k < 8; k++) {
        int   i = lane + k * 32;   // increasing i per lane -> '>' keeps first max
        float v = p[i];
        if (v > best) { best = v; bi = i; }
    }
    #pragma unroll
    for (int off = 16; off; off >>= 1) {
        float ov = __shfl_down_sync(0xffffffffu, best, off);
        int   oi = __shfl_down_sync(0xffffffffu, bi,   off);
        if (ov > best || (ov == best && oi < bi)) { best = ov; bi = oi; }
    }
    if (lane == 0) {
        g_cell[gw] = (unsigned char)bi;
        atomicAdd(&g_cnt[(gw / NQ) * HW + bi], 1);
    }
}

// ---------------------------------------------------------------------------
// Kernel 2 (single block, 256 threads):
//   1) wsum[e] = mean_h w2[e,h]; bmean = mean_h b2[h]
//   2) per-batch mean distance from the 256-bin histogram (double accum)
//   3) LUT[b][d2] = sum_e relu(t*w1[e]+b1[e]) * wsum[e] + bmean,
//      t = (sqrt(d2)/15) / (mean + 1e-6)
// ---------------------------------------------------------------------------
__global__ void k_lut(const float* __restrict__ w1, const float* __restrict__ b1,
                      const float* __restrict__ w2, const float* __restrict__ b2) {
    __shared__ float  s_w1[E], s_b1[E], s_ws[E];
    __shared__ int    s_cnt[B * HW];
    __shared__ double s_red[256];
    __shared__ float  s_mean[B];
    __shared__ float  s_bm;

    int t = threadIdx.x;

    // wsum (w2 is [E, H] row-major)
    float ws = 0.f;
    #pragma unroll
    for (int h = 0; h < NH; h++) ws += w2[t * NH + h];
    s_ws[t] = ws * (1.0f / NH);
    s_w1[t] = w1[t];
    s_b1[t] = b1[t];
    if (t == 0) {
        float bm = 0.f;
        #pragma unroll
        for (int h = 0; h < NH; h++) bm += b2[h];
        s_bm = bm * (1.0f / NH);
    }
    s_cnt[t]       = g_cnt[t];
    s_cnt[t + 256] = g_cnt[t + 256];
    __syncthreads();

    // mean distance per batch: sum over cell pairs cnt[k]*cnt[l]*sqrt(d2)/15
    for (int b = 0; b < B; b++) {
        double acc = 0.0;
        int ck = s_cnt[b * HW + t];
        if (ck) {
            int kx = t & 15, ky = t >> 4;
            for (int l = 0; l < HW; l++) {
                int cl = s_cnt[b * HW + l];
                if (!cl) continue;
                int dx = kx - (l & 15), dy = ky - (l >> 4);
                acc += (double)(ck * cl) * (double)sqrtf((float)(dx * dx + dy * dy));
            }
        }
        s_red[t] = acc;
        __syncthreads();
        for (int s = 128; s; s >>= 1) {
            if (t < s) s_red[t] += s_red[t + s];
            __syncthreads();
        }
        if (t == 0)
            s_mean[b] = (float)(s_red[0] / 15.0 / ((double)NQ * (double)NQ));
        __syncthreads();
    }

    // Build LUT: B*MAXD2 = 902 entries, 4-way ILP on the reduction chain
    for (int e = t; e < B * MAXD2; e += 256) {
        int   b   = e / MAXD2;
        int   d2  = e - b * MAXD2;
        float dst = sqrtf((float)d2) * (1.0f / 15.0f);
        float tt  = dst / (s_mean[b] + 1e-6f);
        float a0 = 0.f, a1 = 0.f, a2 = 0.f, a3 = 0.f;
        #pragma unroll 4
        for (int i = 0; i < E; i += 4) {
            a0 = fmaf(fmaxf(fmaf(tt, s_w1[i + 0], s_b1[i + 0]), 0.f), s_ws[i + 0], a0);
            a1 = fmaf(fmaxf(fmaf(tt, s_w1[i + 1], s_b1[i + 1]), 0.f), s_ws[i + 1], a1);
            a2 = fmaf(fmaxf(fmaf(tt, s_w1[i + 2], s_b1[i + 2]), 0.f), s_ws[i + 2], a2);
            a3 = fmaf(fmaxf(fmaf(tt, s_w1[i + 3], s_b1[i + 3]), 0.f), s_ws[i + 3], a3);
        }
        g_lut[e] = (a0 + a1) + (a2 + a3) + s_bm;
    }
}

// ---------------------------------------------------------------------------
// Kernel 3: out = attn + lam * lut[d2(cell_i, cell_j)], float4-vectorized.
// Total elements = 2*900*900 = 1,620,000 (divisible by 4).
// ---------------------------------------------------------------------------
__global__ void k_out(const float4* __restrict__ attn, const float* __restrict__ lam,
                      float4* __restrict__ out) {
    const int totalv = (B * NQ * NQ) / 4;  // 405000
    int v = blockIdx.x * blockDim.x + threadIdx.x;
    if (v >= totalv) return;

    float  la = __ldg(lam);
    float4 a  = attn[v];
    float  av[4] = {a.x, a.y, a.z, a.w};
    float  r[4];
    int base = v * 4;
    #pragma unroll
    for (int k = 0; k < 4; k++) {
        int idx = base + k;
        int b   = idx / (NQ * NQ);
        int rem = idx - b * (NQ * NQ);
        int i   = rem / NQ;
        int j   = rem - i * NQ;
        int ci  = g_cell[b * NQ + i];
        int cj  = g_cell[b * NQ + j];
        int dx  = (ci & 15) - (cj & 15);
        int dy  = (ci >> 4) - (cj >> 4);
        r[k] = fmaf(la, g_lut[b * MAXD2 + dx * dx + dy * dy], av[k]);
    }
    out[v] = make_float4(r[0], r[1], r[2], r[3]);
}

// ---------------------------------------------------------------------------
// Launch
// Inputs (metadata order): attn_scores[2*900*900] f32, reference_points
// [2*900*16*16] f32, lam[1] f32, w1[256] f32, b1[256] f32, w2[256*8] f32,
// b2[8] f32. Output: [2*900*900] f32.
// ---------------------------------------------------------------------------
extern "C" void kernel_launch(void* const* d_in, const int* in_sizes, int n_in,
                              void* d_out, int out_size) {
    const float* attn = (const float*)d_in[0];
    const float* rp   = (const float*)d_in[1];
    const float* lam  = (const float*)d_in[2];
    const float* w1   = (const float*)d_in[3];
    const float* b1   = (const float*)d_in[4];
    const float* w2   = (const float*)d_in[5];
    const float* b2   = (const float*)d_in[6];
    float*       out  = (float*)d_out;

    k_init<<<(B * HW + 255) / 256, 256>>>();

    int warps = B * NQ;                       // 1800 warps
    k_argmax<<<(warps * 32 + 255) / 256, 256>>>(rp);

    k_lut<<<1, 256>>>(w1, b1, w2, b2);

    int totalv = (B * NQ * NQ) / 4;           // 405000
    k_out<<<(totalv + 255) / 256, 256>>>((const float4*)attn, lam, (float4*)out);
}

// round 2
// speedup vs baseline: 1.0101x; 1.0101x over previous
#include <cuda_runtime.h>

#define B   2
#define NQ  900
#define HW  256      // 16*16 argmax domain
#define E   256      // embed dim
#define NH  8        // heads
#define MAXD2 451    // dx^2+dy^2, dx,dy in [-15,15] -> max 450

// Scratch (no allocations allowed -> __device__ globals)
__device__ unsigned char g_cell[B * NQ];   // argmax cell index (iy*16+ix) per (b,q)
__device__ int           g_cnt[B * HW];    // cell histogram per batch
__device__ float         g_lut[B * MAXD2]; // bias_mean as function of integer d2
__device__ float         g_mean[B];        // per-batch mean distance
__device__ float         g_ws[E];          // mean_h w2[e,h]
__device__ float         g_bm;             // mean_h b2[h]

// ---------------------------------------------------------------------------
// Kernel 0: zero histogram
// ---------------------------------------------------------------------------
__global__ void k_init() {
    int t = blockIdx.x * blockDim.x + threadIdx.x;
    if (t < B * HW) g_cnt[t] = 0;
}

// ---------------------------------------------------------------------------
// Kernel 1: per-(b,q) argmax over 256 values (one warp each), first-index
// tiebreak to match jnp.argmax. Also builds the cell histogram.
// ---------------------------------------------------------------------------
__global__ void k_argmax(const float* __restrict__ rp) {
    int gw   = (blockIdx.x * blockDim.x + threadIdx.x) >> 5;  // global warp id
    int lane = threadIdx.x & 31;
    if (gw >= B * NQ) return;

    const float* p = rp + (size_t)gw * HW;
    float best = -__int_as_float(0x7f800000); // -inf
    int   bi   = 0;
    #pragma unroll
    for (int k = 0; k < 8; k++) {
        int   i = lane + k * 32;   // increasing i per lane -> '>' keeps first max
        float v = p[i];
        if (v > best) { best = v; bi = i; }
    }
    #pragma unroll
    for (int off = 16; off; off >>= 1) {
        float ov = __shfl_down_sync(0xffffffffu, best, off);
        int   oi = __shfl_down_sync(0xffffffffu, bi,   off);
        if (ov > best || (ov == best && oi < bi)) { best = ov; bi = oi; }
    }
    if (lane == 0) {
        g_cell[gw] = (unsigned char)bi;
        atomicAdd(&g_cnt[(gw / NQ) * HW + bi], 1);
    }
}

// ---------------------------------------------------------------------------
// Kernel 2 (single block, 256 threads, CHEAP):
//   - g_ws[e] = mean_h w2[e,h];  g_bm = mean_h b2[h]
//   - per-batch mean distance from the 256-bin histogram (double accum)
// ---------------------------------------------------------------------------
__global__ void k_mean(const float* __restrict__ w2, const float* __restrict__ b2) {
    __shared__ int    s_cnt[B * HW];
    __shared__ double s_red[256];

    int t = threadIdx.x;

    // weight preprocessing (w2 is [E, H] row-major)
    float ws = 0.f;
    #pragma unroll
    for (int h = 0; h < NH; h++) ws += w2[t * NH + h];
    g_ws[t] = ws * (1.0f / NH);
    if (t == 0) {
        float bm = 0.f;
        #pragma unroll
        for (int h = 0; h < NH; h++) bm += b2[h];
        g_bm = bm * (1.0f / NH);
    }
    s_cnt[t]       = g_cnt[t];
    s_cnt[t + 256] = g_cnt[t + 256];
    __syncthreads();

    // mean distance per batch: sum over cell pairs cnt[k]*cnt[l]*sqrt(d2)/15
    for (int b = 0; b < B; b++) {
        double acc = 0.0;
        int ck = s_cnt[b * HW + t];
        if (ck) {
            int kx = t & 15, ky = t >> 4;
            #pragma unroll 4
            for (int l = 0; l < HW; l++) {
                int cl = s_cnt[b * HW + l];
                int dx = kx - (l & 15), dy = ky - (l >> 4);
                acc += (double)(ck * cl) * (double)sqrtf((float)(dx * dx + dy * dy));
            }
        }
        s_red[t] = acc;
        __syncthreads();
        for (int s = 128; s; s >>= 1) {
            if (t < s) s_red[t] += s_red[t + s];
            __syncthreads();
        }
        if (t == 0)
            g_mean[b] = (float)(s_red[0] / 15.0 / ((double)NQ * (double)NQ));
        __syncthreads();
    }
}

// ---------------------------------------------------------------------------
// Kernel 3: LUT build, ONE WARP PER ENTRY (902 warps spread across SMs).
//   LUT[b][d2] = sum_e relu(t*w1[e]+b1[e]) * ws[e] + bm,
//   t = (sqrt(d2)/15) / (mean[b] + 1e-6)
// ---------------------------------------------------------------------------
__global__ void k_lut(const float* __restrict__ w1, const float* __restrict__ b1) {
    int warp = (blockIdx.x * blockDim.x + threadIdx.x) >> 5;
    int lane = threadIdx.x & 31;
    if (warp >= B * MAXD2) return;

    int   b   = warp / MAXD2;
    int   d2  = warp - b * MAXD2;
    float dst = sqrtf((float)d2) * (1.0f / 15.0f);
    float tt  = dst / (g_mean[b] + 1e-6f);

    float acc = 0.f;
    #pragma unroll
    for (int k = 0; k < 8; k++) {
        int i = lane + k * 32;
        acc = fmaf(fmaxf(fmaf(tt, w1[i], b1[i]), 0.f), g_ws[i], acc);
    }
    #pragma unroll
    for (int off = 16; off; off >>= 1)
        acc += __shfl_down_sync(0xffffffffu, acc, off);
    if (lane == 0) g_lut[warp] = acc + g_bm;
}

// ---------------------------------------------------------------------------
// Kernel 4: out = attn + lam * lut[d2(cell_i, cell_j)].
// One block per (b,i) row: no integer division, ci loaded once, cj as uchar4.
// Row = 900 floats = 225 float4 (225 active threads of 256).
// ---------------------------------------------------------------------------
__global__ void k_out(const float* __restrict__ attn, const float* __restrict__ lam,
                      float* __restrict__ out) {
    int row = blockIdx.x;            // 0 .. B*NQ-1
    int b   = row >= NQ ? 1 : 0;
    int t   = threadIdx.x;
    if (t >= NQ / 4) return;         // 225 vectors per row

    float la = __ldg(lam);
    int  ci  = g_cell[row];
    int  cix = ci & 15, ciy = ci >> 4;
    const float* lutb = g_lut + b * MAXD2;

    // cj for columns 4t..4t+3 (g_cell + b*900 is 4-byte aligned: 900 % 4 == 0)
    uchar4 cj4 = *(const uchar4*)(g_cell + b * NQ + t * 4);
    unsigned char cj[4] = {cj4.x, cj4.y, cj4.z, cj4.w};

    const float4* arow = (const float4*)(attn + (size_t)row * NQ);
    float4*       orow = (float4*)(out  + (size_t)row * NQ);
    float4 a = arow[t];
    float av[4] = {a.x, a.y, a.z, a.w};
    float r[4];
    #pragma unroll
    for (int k = 0; k < 4; k++) {
        int dx = cix - (cj[k] & 15);
        int dy = ciy - (cj[k] >> 4);
        r[k] = fmaf(la, lutb[dx * dx + dy * dy], av[k]);
    }
    orow[t] = make_float4(r[0], r[1], r[2], r[3]);
}

// ---------------------------------------------------------------------------
// Launch
// Inputs: attn[2*900*900] f32, ref_pts[2*900*256] f32, lam[1], w1[256],
// b1[256], w2[256*8], b2[8]. Output: [2*900*900] f32.
// ---------------------------------------------------------------------------
extern "C" void kernel_launch(void* const* d_in, const int* in_sizes, int n_in,
                              void* d_out, int out_size) {
    const float* attn = (const float*)d_in[0];
    const float* rp   = (const float*)d_in[1];
    const float* lam  = (const float*)d_in[2];
    const float* w1   = (const float*)d_in[3];
    const float* b1   = (const float*)d_in[4];
    const float* w2   = (const float*)d_in[5];
    const float* b2   = (const float*)d_in[6];
    float*       out  = (float*)d_out;

    k_init<<<2, 256>>>();
    k_argmax<<<(B * NQ * 32 + 255) / 256, 256>>>(rp);
    k_mean<<<1, 256>>>(w2, b2);
    k_lut<<<(B * MAXD2 * 32 + 255) / 256, 256>>>(w1, b1);
    k_out<<<B * NQ, 256>>>(attn, lam, out);
}

// round 3
// speedup vs baseline: 5.4347x; 5.3806x over previous
#include <cuda_runtime.h>

#define B   2
#define NQ  900
#define HW  256      // 16*16 argmax domain
#define E   256      // embed dim
#define NH  8        // heads
#define MAXD2 451    // dx^2+dy^2, dx,dy in [-15,15] -> max 450

// Scratch (no allocations allowed -> __device__ globals)
__device__ unsigned char g_cell[B * NQ];    // argmax cell index per (b,q)
__device__ int           g_cnt[B * HW];     // cell histogram per batch
__device__ int           g_p[B * MAXD2];    // pair-count histogram over d2 (EXACT)
__device__ float         g_lut[B * MAXD2];  // bias_mean as function of integer d2

// ---------------------------------------------------------------------------
// Kernel 0: zero histograms (512 + 902 ints)
// ---------------------------------------------------------------------------
__global__ void k_init() {
    int t = blockIdx.x * blockDim.x + threadIdx.x;
    if (t < B * HW)    g_cnt[t] = 0;
    if (t < B * MAXD2) g_p[t]   = 0;
}

// ---------------------------------------------------------------------------
// Kernel 1: per-(b,q) argmax over 256 values (one warp each), first-index
// tiebreak to match jnp.argmax. Also builds the cell histogram.
// ---------------------------------------------------------------------------
__global__ void k_argmax(const float* __restrict__ rp) {
    int gw   = (blockIdx.x * blockDim.x + threadIdx.x) >> 5;
    int lane = threadIdx.x & 31;
    if (gw >= B * NQ) return;

    const float* p = rp + (size_t)gw * HW;
    float best = -__int_as_float(0x7f800000); // -inf
    int   bi   = 0;
    #pragma unroll
    for (int k = 0; k < 8; k++) {
        int   i = lane + k * 32;   // increasing i per lane -> '>' keeps first max
        float v = p[i];
        if (v > best) { best = v; bi = i; }
    }
    #pragma unroll
    for (int off = 16; off; off >>= 1) {
        float ov = __shfl_down_sync(0xffffffffu, best, off);
        int   oi = __shfl_down_sync(0xffffffffu, bi,   off);
        if (ov > best || (ov == best && oi < bi)) { best = ov; bi = oi; }
    }
    if (lane == 0) {
        g_cell[gw] = (unsigned char)bi;
        atomicAdd(&g_cnt[(gw / NQ) * HW + bi], 1);
    }
}

// ---------------------------------------------------------------------------
// Kernel 2: pair-count histogram over integer d2. One block per (b, cell k);
// thread l handles pair (k,l). All-integer -> exact & deterministic.
// Grid: B*HW = 512 blocks x 256 threads (spread across the chip).
// ---------------------------------------------------------------------------
__global__ void k_pair() {
    __shared__ int sP[MAXD2];
    __shared__ int sCnt[HW];

    int b = blockIdx.x >> 8;       // /256
    int k = blockIdx.x & 255;
    int t = threadIdx.x;

    sP[t] = 0;
    if (t + 256 < MAXD2) sP[t + 256] = 0;
    sCnt[t] = g_cnt[b * HW + t];
    __syncthreads();

    int ck = sCnt[k];
    if (ck) {
        int cl = sCnt[t];
        if (cl) {
            int dx = (k & 15) - (t & 15);
            int dy = (k >> 4) - (t >> 4);
            atomicAdd(&sP[dx * dx + dy * dy], ck * cl);
        }
    }
    __syncthreads();

    int v = sP[t];
    if (v) atomicAdd(&g_p[b * MAXD2 + t], v);
    if (t + 256 < MAXD2) {
        v = sP[t + 256];
        if (v) atomicAdd(&g_p[b * MAXD2 + t + 256], v);
    }
}

// ---------------------------------------------------------------------------
// Kernel 3: LUT build. Each block first (redundantly, deterministically)
// computes both batch means from the 451-bin pair histogram (double, fixed
// tree order), then one warp per LUT entry evaluates the collapsed MLP.
//   LUT[b][d2] = sum_e relu(t*w1[e]+b1[e]) * mean_h(w2[e,h]) + mean_h(b2),
//   t = (sqrt(d2)/15) / (mean[b] + 1e-6)
// ---------------------------------------------------------------------------
__global__ void k_lut(const float* __restrict__ w1, const float* __restrict__ b1,
                      const float* __restrict__ w2, const float* __restrict__ b2) {
    __shared__ double s_red[256];
    __shared__ float  s_mean[B];

    int t = threadIdx.x;

    // --- batch means (451 sqrt terms each; trivial) ---
    for (int b = 0; b < B; b++) {
        double acc = 0.0;
        for (int bin = t; bin < MAXD2; bin += 256)
            acc += (double)g_p[b * MAXD2 + bin] * (double)sqrtf((float)bin);
        s_red[t] = acc;
        __syncthreads();
        for (int s = 128; s; s >>= 1) {
            if (t < s) s_red[t] += s_red[t + s];
            __syncthreads();
        }
        if (t == 0)
            s_mean[b] = (float)(s_red[0] / 15.0 / ((double)NQ * (double)NQ));
        __syncthreads();
    }

    // --- LUT entries: one warp per entry ---
    int lane  = t & 31;
    int gwarp = blockIdx.x * (blockDim.x >> 5) + (t >> 5);
    if (gwarp >= B * MAXD2) return;

    int   b   = gwarp >= MAXD2 ? 1 : 0;
    int   d2  = gwarp - b * MAXD2;
    float dst = sqrtf((float)d2) * (1.0f / 15.0f);
    float tt  = dst / (s_mean[b] + 1e-6f);

    float bm = 0.f;
    #pragma unroll
    for (int h = 0; h < NH; h++) bm += b2[h];
    bm *= (1.0f / NH);

    float acc = 0.f;
    #pragma unroll
    for (int k = 0; k < 8; k++) {
        int i = lane + k * 32;
        // ws[i] = mean over heads of w2 row i (coalesced float4 loads)
        const float4* w2r = (const float4*)(w2 + i * NH);
        float4 wa = w2r[0], wb = w2r[1];
        float ws = ((wa.x + wa.y) + (wa.z + wa.w) +
                    (wb.x + wb.y) + (wb.z + wb.w)) * (1.0f / NH);
        acc = fmaf(fmaxf(fmaf(tt, w1[i], b1[i]), 0.f), ws, acc);
    }
    #pragma unroll
    for (int off = 16; off; off >>= 1)
        acc += __shfl_down_sync(0xffffffffu, acc, off);
    if (lane == 0) g_lut[gwarp] = acc + bm;
}

// ---------------------------------------------------------------------------
// Kernel 4: out = attn + lam * lut[d2(cell_i, cell_j)].
// Two rows per block (512 threads), LUT staged in shared, cj as uchar4,
// no integer divisions on the hot path.
// ---------------------------------------------------------------------------
__global__ void k_out(const float* __restrict__ attn, const float* __restrict__ lam,
                      float* __restrict__ out) {
    __shared__ float sLut[MAXD2];

    int t    = threadIdx.x;
    int row0 = blockIdx.x * 2;            // rows row0, row0+1 (same batch always)
    int b    = row0 >= NQ ? 1 : 0;

    // stage this batch's LUT
    if (t < MAXD2) sLut[t] = g_lut[b * MAXD2 + t];
    __syncthreads();

    int half = t >> 8;                    // 0 or 1 -> which row
    int v    = t & 255;                   // vector index within row
    if (v >= NQ / 4) return;              // 225 vectors per row

    int row = row0 + half;
    float la = __ldg(lam);
    int  ci  = g_cell[row];
    int  cix = ci & 15, ciy = ci >> 4;

    uchar4 cj4 = *(const uchar4*)(g_cell + b * NQ + v * 4);
    unsigned char cj[4] = {cj4.x, cj4.y, cj4.z, cj4.w};

    const float4* arow = (const float4*)(attn + (size_t)row * NQ);
    float4*       orow = (float4*)(out  + (size_t)row * NQ);
    float4 a = arow[v];
    float av[4] = {a.x, a.y, a.z, a.w};
    float r[4];
    #pragma unroll
    for (int k = 0; k < 4; k++) {
        int dx = cix - (cj[k] & 15);
        int dy = ciy - (cj[k] >> 4);
        r[k] = fmaf(la, sLut[dx * dx + dy * dy], av[k]);
    }
    orow[v] = make_float4(r[0], r[1], r[2], r[3]);
}

// ---------------------------------------------------------------------------
// Launch
// Inputs: attn[2*900*900] f32, ref_pts[2*900*256] f32, lam[1], w1[256],
// b1[256], w2[256*8], b2[8]. Output: [2*900*900] f32.
// ---------------------------------------------------------------------------
extern "C" void kernel_launch(void* const* d_in, const int* in_sizes, int n_in,
                              void* d_out, int out_size) {
    const float* attn = (const float*)d_in[0];
    const float* rp   = (const float*)d_in[1];
    const float* lam  = (const float*)d_in[2];
    const float* w1   = (const float*)d_in[3];
    const float* b1   = (const float*)d_in[4];
    const float* w2   = (const float*)d_in[5];
    const float* b2   = (const float*)d_in[6];
    float*       out  = (float*)d_out;

    k_init<<<4, 256>>>();
    k_argmax<<<(B * NQ * 32 + 255) / 256, 256>>>(rp);
    k_pair<<<B * HW, 256>>>();
    k_lut<<<(B * MAXD2 + 7) / 8, 256>>>(w1, b1, w2, b2);
    k_out<<<B * NQ / 2, 512>>>(attn, lam, out);
}